// round 2
// baseline (speedup 1.0000x reference)
#include <cuda_runtime.h>
#include <math.h>

#define BB   8
#define NN   2048
#define DIMM 1024
#define HH   16
#define MM   (BB*NN)   /* 16384 rows */
#define CH   32        /* scan time-chunk */

// ---------------- scratch (static device globals; no allocation) ----------------
__device__ float g_pq[(size_t)MM*DIMM];
__device__ float g_pk[(size_t)MM*DIMM];
__device__ float g_pv[(size_t)MM*DIMM];
__device__ float g_q [(size_t)MM*DIMM];
__device__ float g_k [(size_t)MM*DIMM];
__device__ float g_v [(size_t)MM*DIMM];
__device__ float g_o [(size_t)MM*DIMM];
__device__ float g_a [(size_t)MM*HH];
__device__ float g_b [(size_t)MM*HH];

// ---------------- helpers ----------------
__device__ __forceinline__ float siluf(float x){ return x / (1.f + __expf(-x)); }
__device__ __forceinline__ float sigmf(float x){ return 1.f / (1.f + __expf(-x)); }

__device__ __forceinline__ unsigned long long pk2(float x){
  unsigned long long r;
  asm("mov.b64 %0, {%1, %2};" : "=l"(r) : "f"(x), "f"(x));
  return r;
}
__device__ __forceinline__ void ffma2(unsigned long long &d, unsigned long long a, unsigned long long b){
  asm("fma.rn.f32x2 %0, %1, %2, %0;" : "+l"(d) : "l"(a), "l"(b));
}
__device__ __forceinline__ float2 upk2(unsigned long long v){
  float2 r; asm("mov.b64 {%0, %1}, %2;" : "=f"(r.x), "=f"(r.y) : "l"(v)); return r;
}

// ---------------- big GEMM: C[m][n] = act( sum_k A[m][k]*W[n][k] + bias[n] ) ----
// K = 1024 fixed. grid(8, M/128), block 256. f32x2 packed FMAs (pairs along M).
__global__ __launch_bounds__(256) void gemm1024(
    const float* __restrict__ A, const float* __restrict__ W,
    const float* __restrict__ bias, float* __restrict__ C, int doSilu)
{
  __shared__ float As[16][128];
  __shared__ float Ws[16][128];
  const int tid = threadIdx.x;
  const int m0  = blockIdx.y << 7;
  const int n0  = blockIdx.x << 7;
  const int lr  = tid >> 2;           // 0..63
  const int lc  = (tid & 3) << 2;     // 0,4,8,12
  const int tm0 = (tid >> 4) << 3;    // 0..120
  const int tn0 = (tid & 15) << 3;    // 0..120

  unsigned long long acc[4][8];
#pragma unroll
  for (int i = 0; i < 4; i++)
#pragma unroll
    for (int j = 0; j < 8; j++) acc[i][j] = 0ull;

  const float* Ap = A + (size_t)(m0 + lr) * DIMM + lc;
  const float* Wp = W + (size_t)(n0 + lr) * DIMM + lc;

  for (int k0 = 0; k0 < 1024; k0 += 16) {
    float4 a0 = *(const float4*)(Ap + k0);
    float4 a1 = *(const float4*)(Ap + (size_t)64*DIMM + k0);
    float4 w0 = *(const float4*)(Wp + k0);
    float4 w1 = *(const float4*)(Wp + (size_t)64*DIMM + k0);
    __syncthreads();
    As[lc+0][lr]    = a0.x; As[lc+1][lr]    = a0.y; As[lc+2][lr]    = a0.z; As[lc+3][lr]    = a0.w;
    As[lc+0][lr+64] = a1.x; As[lc+1][lr+64] = a1.y; As[lc+2][lr+64] = a1.z; As[lc+3][lr+64] = a1.w;
    Ws[lc+0][lr]    = w0.x; Ws[lc+1][lr]    = w0.y; Ws[lc+2][lr]    = w0.z; Ws[lc+3][lr]    = w0.w;
    Ws[lc+0][lr+64] = w1.x; Ws[lc+1][lr+64] = w1.y; Ws[lc+2][lr+64] = w1.z; Ws[lc+3][lr+64] = w1.w;
    __syncthreads();
#pragma unroll
    for (int kk = 0; kk < 16; kk++) {
      unsigned long long aa[4];
#pragma unroll
      for (int i = 0; i < 4; i++)
        aa[i] = *(const unsigned long long*)&As[kk][tm0 + (i << 1)];
      float4 wv0 = *(const float4*)&Ws[kk][tn0];
      float4 wv1 = *(const float4*)&Ws[kk][tn0 + 4];
      unsigned long long wd[8];
      wd[0]=pk2(wv0.x); wd[1]=pk2(wv0.y); wd[2]=pk2(wv0.z); wd[3]=pk2(wv0.w);
      wd[4]=pk2(wv1.x); wd[5]=pk2(wv1.y); wd[6]=pk2(wv1.z); wd[7]=pk2(wv1.w);
#pragma unroll
      for (int i = 0; i < 4; i++)
#pragma unroll
        for (int j = 0; j < 8; j++) ffma2(acc[i][j], aa[i], wd[j]);
    }
  }

  float bv[8];
#pragma unroll
  for (int j = 0; j < 8; j++) bv[j] = bias[n0 + tn0 + j];
#pragma unroll
  for (int i = 0; i < 4; i++) {
    float lo[8], hi[8];
#pragma unroll
    for (int j = 0; j < 8; j++) {
      float2 p = upk2(acc[i][j]);
      lo[j] = p.x + bv[j];
      hi[j] = p.y + bv[j];
      if (doSilu) { lo[j] = siluf(lo[j]); hi[j] = siluf(hi[j]); }
    }
    const int m = m0 + tm0 + (i << 1);
    float* c0 = C + (size_t)m * DIMM + n0 + tn0;
    *(float4*)(c0)        = make_float4(lo[0], lo[1], lo[2], lo[3]);
    *(float4*)(c0 + 4)    = make_float4(lo[4], lo[5], lo[6], lo[7]);
    *(float4*)(c0 + DIMM)     = make_float4(hi[0], hi[1], hi[2], hi[3]);
    *(float4*)(c0 + DIMM + 4) = make_float4(hi[4], hi[5], hi[6], hi[7]);
  }
}

// ---------------- gate projections: a = sigmoid(x@Wa^T+ba), b = sigmoid(x@Wb^T+bb) --
__global__ __launch_bounds__(256) void gate_gemm(
    const float* __restrict__ X, const float* __restrict__ Wa, const float* __restrict__ ba,
    const float* __restrict__ Wb, const float* __restrict__ bbias,
    float* __restrict__ Ga, float* __restrict__ Gb)
{
  __shared__ float Xs[32][129];
  __shared__ float Ws[32][33];
  const int tid = threadIdx.x;
  const int m0  = blockIdx.x << 7;
  const int tm0 = (tid >> 4) << 3;
  const int tn0 = (tid & 15) << 1;

  float acc[8][2];
#pragma unroll
  for (int i = 0; i < 8; i++) { acc[i][0] = 0.f; acc[i][1] = 0.f; }

  for (int k0 = 0; k0 < 1024; k0 += 32) {
    __syncthreads();
#pragma unroll
    for (int ii = 0; ii < 4; ii++) {
      int idx = tid + (ii << 8);
      int r = idx >> 3, c4 = (idx & 7) << 2;
      float4 v = *(const float4*)&X[(size_t)(m0 + r) * DIMM + k0 + c4];
      Xs[c4+0][r] = v.x; Xs[c4+1][r] = v.y; Xs[c4+2][r] = v.z; Xs[c4+3][r] = v.w;
    }
    if (tid < 256) {
      int n = tid >> 3, c4 = (tid & 7) << 2;
      const float* wp = (n < 16) ? (Wa + (size_t)n * DIMM) : (Wb + (size_t)(n - 16) * DIMM);
      float4 v = *(const float4*)&wp[k0 + c4];
      Ws[c4+0][n] = v.x; Ws[c4+1][n] = v.y; Ws[c4+2][n] = v.z; Ws[c4+3][n] = v.w;
    }
    __syncthreads();
#pragma unroll
    for (int kk = 0; kk < 32; kk++) {
      float wf0 = Ws[kk][tn0], wf1 = Ws[kk][tn0 + 1];
#pragma unroll
      for (int i = 0; i < 8; i++) {
        float av = Xs[kk][tm0 + i];
        acc[i][0] = fmaf(av, wf0, acc[i][0]);
        acc[i][1] = fmaf(av, wf1, acc[i][1]);
      }
    }
  }
#pragma unroll
  for (int j = 0; j < 2; j++) {
    int col = tn0 + j;
    float bi = (col < 16) ? ba[col] : bbias[col - 16];
    float* dst = (col < 16) ? Ga : Gb;
    int cc = col & 15;
#pragma unroll
    for (int i = 0; i < 8; i++) {
      int row = m0 + tm0 + i;
      dst[(size_t)row * 16 + cc] = sigmf(acc[i][j] + bi);
    }
  }
}

// ---------------- depthwise conv (K=4, causal-ish window t-2..t+1) + silu --------
__global__ __launch_bounds__(256) void conv_silu_kernel(
    const float* __restrict__ P, const float* __restrict__ wc, float* __restrict__ Y)
{
  const int c  = (blockIdx.x << 8) + threadIdx.x;
  const int b  = blockIdx.z;
  const int t0 = blockIdx.y << 7;   // 128 timesteps per block
  const float w0 = wc[c*4+0], w1 = wc[c*4+1], w2 = wc[c*4+2], w3 = wc[c*4+3];
  const float* base  = P + (size_t)b * NN * DIMM + c;
  float*       ybase = Y + (size_t)b * NN * DIMM + c;
  float xm2 = (t0 >= 2) ? base[(size_t)(t0-2)*DIMM] : 0.f;
  float xm1 = (t0 >= 1) ? base[(size_t)(t0-1)*DIMM] : 0.f;
  float x0  = base[(size_t)t0 * DIMM];
#pragma unroll 4
  for (int t = t0; t < t0 + 128; t++) {
    float xp1 = (t + 1 < NN) ? base[(size_t)(t+1)*DIMM] : 0.f;
    float y = w0*xm2 + w1*xm1 + w2*x0 + w3*xp1;
    ybase[(size_t)t * DIMM] = siluf(y);
    xm2 = xm1; xm1 = x0; x0 = xp1;
  }
}

// ---------------- row l2norm (in place): row /= (||row||_2 + 1e-6) --------------
__global__ __launch_bounds__(256) void l2norm_kernel(float* __restrict__ X)
{
  __shared__ float red[8];
  float4* p = (float4*)(X + (size_t)blockIdx.x * DIMM);
  const int tid = threadIdx.x;
  float4 v = p[tid];
  float s = v.x*v.x + v.y*v.y + v.z*v.z + v.w*v.w;
#pragma unroll
  for (int o = 16; o > 0; o >>= 1) s += __shfl_xor_sync(0xffffffffu, s, o);
  if ((tid & 31) == 0) red[tid >> 5] = s;
  __syncthreads();
  float tot = red[0]+red[1]+red[2]+red[3]+red[4]+red[5]+red[6]+red[7];
  float inv = 1.f / (sqrtf(tot) + 1e-6f);
  v.x *= inv; v.y *= inv; v.z *= inv; v.w *= inv;
  p[tid] = v;
}

// ---------------- gated delta-rule scan ----------------------------------------
// grid 128 (b*16+h), block 256. Thread (e,g): e=tid&63 column, g=tid>>6 owns rows
// [16g,16g+16) of S[:,e]. S_new = a*S + (b*(v - a*S k)) ⊗ k ; o = q^T S_new.
__global__ __launch_bounds__(256) void scan_kernel(
    const float* __restrict__ Q, const float* __restrict__ Kv, const float* __restrict__ V,
    const float* __restrict__ A, const float* __restrict__ Bg, float* __restrict__ O)
{
  __shared__ float shq[CH][64], shk[CH][64], shv[CH][64];
  __shared__ float sha[CH], shb[CH];
  __shared__ float mat[64][68];
  __shared__ float part[64][4];
  __shared__ float part2[64][4];
  __shared__ float coefsh[64];
  const int tid = threadIdx.x;
  const int e = tid & 63, g = tid >> 6;
  const int bh = blockIdx.x;
  const int b = bh >> 4, h = bh & 15;
  const size_t base = ((size_t)b * NN) * DIMM + h * 64;
  float S[16];
#pragma unroll
  for (int i = 0; i < 16; i++) S[i] = 0.f;

  for (int t0 = 0; t0 < NN; t0 += CH) {
    __syncthreads();
    for (int idx = tid; idx < CH*64; idx += 256) {
      int i = idx >> 6, ee = idx & 63;
      size_t off = base + (size_t)(t0 + i) * DIMM + ee;
      shq[i][ee] = Q[off]; shk[i][ee] = Kv[off]; shv[i][ee] = V[off];
    }
    if (tid < CH) {
      size_t off = ((size_t)b * NN + t0 + tid) * 16 + h;
      sha[tid] = A[off]; shb[tid] = Bg[off];
    }
    __syncthreads();

    for (int i = 0; i < CH; i++) {
      const float ke = shk[i][e];
      const float aT = sha[i], bT = shb[i];
#pragma unroll
      for (int j = 0; j < 16; j++) mat[16*g + j][e] = S[j] * ke;
      __syncthreads();
      // quarter row-sum for Sk[e]
      const float4* rp = (const float4*)&mat[e][16*g];
      float4 p0 = rp[0], p1 = rp[1], p2 = rp[2], p3 = rp[3];
      part[e][g] = (p0.x+p0.y+p0.z+p0.w) + (p1.x+p1.y+p1.z+p1.w)
                 + (p2.x+p2.y+p2.z+p2.w) + (p3.x+p3.y+p3.z+p3.w);
      __syncthreads();
      if (g == 0) {
        float4 pr = *(const float4*)&part[e][0];
        float Sk = pr.x + pr.y + pr.z + pr.w;
        coefsh[e] = bT * (shv[i][e] - aT * Sk);
      }
      __syncthreads();
      float op = 0.f;
#pragma unroll
      for (int j4 = 0; j4 < 4; j4++) {
        float4 cf = *(const float4*)&coefsh[16*g + 4*j4];
        float4 qv = *(const float4*)&shq[i][16*g + 4*j4];
        int j = 4*j4;
        S[j+0] = aT*S[j+0] + cf.x*ke; op = fmaf(qv.x, S[j+0], op);
        S[j+1] = aT*S[j+1] + cf.y*ke; op = fmaf(qv.y, S[j+1], op);
        S[j+2] = aT*S[j+2] + cf.z*ke; op = fmaf(qv.z, S[j+2], op);
        S[j+3] = aT*S[j+3] + cf.w*ke; op = fmaf(qv.w, S[j+3], op);
      }
      part2[e][g] = op;
      __syncthreads();
      if (g == 0) {
        float4 pr = *(const float4*)&part2[e][0];
        O[base + (size_t)(t0 + i) * DIMM + e] = pr.x + pr.y + pr.z + pr.w;
      }
    }
  }
}

// ---------------- launch ---------------------------------------------------------
extern "C" void kernel_launch(void* const* d_in, const int* in_sizes, int n_in,
                              void* d_out, int out_size) {
  const float* x      = (const float*)d_in[0];
  const float* Wq     = (const float*)d_in[1];
  const float* bq     = (const float*)d_in[2];
  const float* Wk     = (const float*)d_in[3];
  const float* bk     = (const float*)d_in[4];
  const float* Wv     = (const float*)d_in[5];
  const float* bv     = (const float*)d_in[6];
  const float* Wa     = (const float*)d_in[7];
  const float* ba     = (const float*)d_in[8];
  const float* Wb     = (const float*)d_in[9];
  const float* bb     = (const float*)d_in[10];
  const float* conv_q = (const float*)d_in[11];
  const float* conv_k = (const float*)d_in[12];
  const float* conv_v = (const float*)d_in[13];
  const float* Wo     = (const float*)d_in[14];
  const float* bo     = (const float*)d_in[15];
  float* out = (float*)d_out;

  void *pq, *pk, *pv, *q, *k, *v, *o, *ga, *gb;
  cudaGetSymbolAddress(&pq, g_pq);
  cudaGetSymbolAddress(&pk, g_pk);
  cudaGetSymbolAddress(&pv, g_pv);
  cudaGetSymbolAddress(&q,  g_q);
  cudaGetSymbolAddress(&k,  g_k);
  cudaGetSymbolAddress(&v,  g_v);
  cudaGetSymbolAddress(&o,  g_o);
  cudaGetSymbolAddress(&ga, g_a);
  cudaGetSymbolAddress(&gb, g_b);

  dim3 ggrid(8, MM/128);
  gemm1024<<<ggrid, 256>>>(x, Wq, bq, (float*)pq, 1);
  gemm1024<<<ggrid, 256>>>(x, Wk, bk, (float*)pk, 1);
  gemm1024<<<ggrid, 256>>>(x, Wv, bv, (float*)pv, 1);
  gate_gemm<<<MM/128, 256>>>(x, Wa, ba, Wb, bb, (float*)ga, (float*)gb);

  dim3 cgrid(DIMM/256, NN/128, BB);
  conv_silu_kernel<<<cgrid, 256>>>((const float*)pq, conv_q, (float*)q);
  conv_silu_kernel<<<cgrid, 256>>>((const float*)pk, conv_k, (float*)k);
  conv_silu_kernel<<<cgrid, 256>>>((const float*)pv, conv_v, (float*)v);

  l2norm_kernel<<<MM, 256>>>((float*)q);
  l2norm_kernel<<<MM, 256>>>((float*)k);

  scan_kernel<<<BB*HH, 256>>>((const float*)q, (const float*)k, (const float*)v,
                              (const float*)ga, (const float*)gb, (float*)o);

  gemm1024<<<ggrid, 256>>>((const float*)o, Wo, bo, out, 0);
}

// round 9
// speedup vs baseline: 1.6171x; 1.6171x over previous
#include <cuda_runtime.h>
#include <cuda_bf16.h>
#include <math.h>
#include <stdint.h>

#define BB   8
#define NN   2048
#define DIMM 1024
#define HH   16
#define MM   (BB*NN)   /* 16384 rows */
#define CH   32        /* scan time-chunk */

// ---------------- scratch (static device globals; no allocation) ----------------
__device__ float g_pq[(size_t)MM*DIMM];
__device__ float g_pk[(size_t)MM*DIMM];
__device__ float g_pv[(size_t)MM*DIMM];
__device__ float g_q [(size_t)MM*DIMM];
__device__ float g_k [(size_t)MM*DIMM];
__device__ float g_v [(size_t)MM*DIMM];
__device__ float g_o [(size_t)MM*DIMM];
__device__ float g_a [(size_t)MM*HH];
__device__ float g_b [(size_t)MM*HH];
__device__ __align__(256) __nv_bfloat16 g_xhi[(size_t)MM*DIMM];
__device__ __align__(256) __nv_bfloat16 g_xlo[(size_t)MM*DIMM];
__device__ __align__(256) __nv_bfloat16 g_ohi[(size_t)MM*DIMM];
__device__ __align__(256) __nv_bfloat16 g_olo[(size_t)MM*DIMM];
__device__ __align__(256) __nv_bfloat16 g_whi[(size_t)DIMM*DIMM];
__device__ __align__(256) __nv_bfloat16 g_wlo[(size_t)DIMM*DIMM];

// ---------------- helpers ----------------
__device__ __forceinline__ float siluf(float x){ return x / (1.f + __expf(-x)); }
__device__ __forceinline__ float sigmf(float x){ return 1.f / (1.f + __expf(-x)); }

__device__ __forceinline__ uint32_t smem_u32(const void* p){
  uint32_t a;
  asm("{ .reg .u64 t; cvta.to.shared.u64 t, %1; cvt.u32.u64 %0, t; }" : "=r"(a) : "l"(p));
  return a;
}
__device__ __forceinline__ void ldsm4(uint32_t* d, uint32_t addr){
  asm volatile("ldmatrix.sync.aligned.m8n8.x4.shared.b16 {%0,%1,%2,%3}, [%4];"
    : "=r"(d[0]),"=r"(d[1]),"=r"(d[2]),"=r"(d[3]) : "r"(addr));
}
__device__ __forceinline__ void mma16816(float* d, const uint32_t* a, const uint32_t* b){
  asm volatile("mma.sync.aligned.m16n8k16.row.col.f32.bf16.bf16.f32 "
    "{%0,%1,%2,%3}, {%4,%5,%6,%7}, {%8,%9}, {%0,%1,%2,%3};"
    : "+f"(d[0]),"+f"(d[1]),"+f"(d[2]),"+f"(d[3])
    : "r"(a[0]),"r"(a[1]),"r"(a[2]),"r"(a[3]), "r"(b[0]),"r"(b[1]));
}

// ---------------- bf16 hi/lo split ----------------
__global__ __launch_bounds__(256) void split_kernel(
    const float* __restrict__ X, __nv_bfloat16* __restrict__ Hp, __nv_bfloat16* __restrict__ Lp, int n4)
{
  int i = blockIdx.x * 256 + threadIdx.x;
  if (i >= n4) return;
  float4 v = ((const float4*)X)[i];
  __nv_bfloat16 h0 = __float2bfloat16(v.x), h1 = __float2bfloat16(v.y);
  __nv_bfloat16 h2 = __float2bfloat16(v.z), h3 = __float2bfloat16(v.w);
  __nv_bfloat16 l0 = __float2bfloat16(v.x - __bfloat162float(h0));
  __nv_bfloat16 l1 = __float2bfloat16(v.y - __bfloat162float(h1));
  __nv_bfloat16 l2 = __float2bfloat16(v.z - __bfloat162float(h2));
  __nv_bfloat16 l3 = __float2bfloat16(v.w - __bfloat162float(h3));
  __nv_bfloat162* Hq = (__nv_bfloat162*)Hp;
  __nv_bfloat162* Lq = (__nv_bfloat162*)Lp;
  Hq[2*i]   = __nv_bfloat162(h0, h1);
  Hq[2*i+1] = __nv_bfloat162(h2, h3);
  Lq[2*i]   = __nv_bfloat162(l0, l1);
  Lq[2*i+1] = __nv_bfloat162(l2, l3);
}

// ---------------- HMMA bf16-split GEMM (mma.sync; B loaded NON-trans) --------
// C[m][n] = act( sum_k A[m][k]*W[n][k] + bias[n] ), A = Ahi+Alo, W = Whi+Wlo.
// W rows are k-contiguous = column-major B, so the B fragment comes from a
// plain (non-trans) ldmatrix over rows = n. (.trans here was the R7 bug.)
// grid(8, M/128), block 256 = 8 warps as 2(M)x4(N); per-warp 64x32 output.
// K in 32 chunks of 32; single 40KB smem stage, register-staged prefetch.
#define KC 32
#define ASTR 40          /* bf16 row stride (80 B, 16B-mult, conflict-free) */

__global__ __launch_bounds__(256, 1) void gemm_mma(
    const __nv_bfloat16* __restrict__ Ahi, const __nv_bfloat16* __restrict__ Alo,
    const __nv_bfloat16* __restrict__ Whi, const __nv_bfloat16* __restrict__ Wlo,
    const float* __restrict__ bias, float* __restrict__ C, int doSilu)
{
  __shared__ __nv_bfloat16 sAh[128*ASTR], sAl[128*ASTR], sWh[128*ASTR], sWl[128*ASTR];

  const int tid  = threadIdx.x;
  const int w    = tid >> 5;
  const int lane = tid & 31;
  const int warp_m = w >> 2;        // 0..1
  const int warp_n = w & 3;         // 0..3
  const int m0 = blockIdx.y << 7;
  const int n0 = blockIdx.x << 7;

  // load mapping: row r, 16-col half
  const int r    = tid >> 1;
  const int gcol = (tid & 1) << 4;  // 0 or 16
  const __nv_bfloat16* pAh = Ahi + (size_t)(m0 + r) * DIMM + gcol;
  const __nv_bfloat16* pAl = Alo + (size_t)(m0 + r) * DIMM + gcol;
  const __nv_bfloat16* pWh = Whi + (size_t)(n0 + r) * DIMM + gcol;
  const __nv_bfloat16* pWl = Wlo + (size_t)(n0 + r) * DIMM + gcol;
  const int soff = r * ASTR + gcol;

  // ldmatrix per-lane addressing (x4: lanes 8i..8i+7 address matrix i)
  const int mmat = lane >> 3, rr = lane & 7;
  const int arowb = warp_m * 64 + ((mmat & 1) << 3) + rr;   // + mt*16
  const int acols = (mmat >> 1) << 3;                       // + ks
  const int browb = warp_n * 32 + ((mmat >> 1) << 3) + rr;  // + np*16
  const int bcols = (mmat & 1) << 3;                        // + ks
  const uint32_t sAhB = smem_u32(sAh), sAlB = smem_u32(sAl);
  const uint32_t sWhB = smem_u32(sWh), sWlB = smem_u32(sWl);

  float acc[4][4][4];
#pragma unroll
  for (int mt = 0; mt < 4; mt++)
#pragma unroll
    for (int nt = 0; nt < 4; nt++)
#pragma unroll
      for (int i = 0; i < 4; i++) acc[mt][nt][i] = 0.f;

  uint4 rAh[2], rAl[2], rWh[2], rWl[2];
  // prologue: chunk 0 -> regs
  rAh[0] = *(const uint4*)(pAh);     rAh[1] = *(const uint4*)(pAh + 8);
  rAl[0] = *(const uint4*)(pAl);     rAl[1] = *(const uint4*)(pAl + 8);
  rWh[0] = *(const uint4*)(pWh);     rWh[1] = *(const uint4*)(pWh + 8);
  rWl[0] = *(const uint4*)(pWl);     rWl[1] = *(const uint4*)(pWl + 8);

  for (int c = 0; c < DIMM / KC; c++) {
    __syncthreads();   // previous compute done; smem free
    *(uint4*)&sAh[soff]     = rAh[0];  *(uint4*)&sAh[soff + 8] = rAh[1];
    *(uint4*)&sAl[soff]     = rAl[0];  *(uint4*)&sAl[soff + 8] = rAl[1];
    *(uint4*)&sWh[soff]     = rWh[0];  *(uint4*)&sWh[soff + 8] = rWh[1];
    *(uint4*)&sWl[soff]     = rWl[0];  *(uint4*)&sWl[soff + 8] = rWl[1];
    if (c + 1 < DIMM / KC) {
      const int ko = (c + 1) * KC;
      rAh[0] = *(const uint4*)(pAh + ko);  rAh[1] = *(const uint4*)(pAh + ko + 8);
      rAl[0] = *(const uint4*)(pAl + ko);  rAl[1] = *(const uint4*)(pAl + ko + 8);
      rWh[0] = *(const uint4*)(pWh + ko);  rWh[1] = *(const uint4*)(pWh + ko + 8);
      rWl[0] = *(const uint4*)(pWl + ko);  rWl[1] = *(const uint4*)(pWl + ko + 8);
    }
    __syncthreads();

#pragma unroll
    for (int ks = 0; ks < KC; ks += 16) {
      uint32_t ah[4][4], al[4][4];
#pragma unroll
      for (int mt = 0; mt < 4; mt++) {
        uint32_t off = (uint32_t)(((arowb + mt * 16) * ASTR + ks + acols) * 2);
        ldsm4(ah[mt], sAhB + off);
        ldsm4(al[mt], sAlB + off);
      }
      uint32_t bh[4][2], bl[4][2];
#pragma unroll
      for (int np = 0; np < 2; np++) {
        uint32_t off = (uint32_t)(((browb + np * 16) * ASTR + ks + bcols) * 2);
        uint32_t t[4];
        ldsm4(t, sWhB + off);   // NON-trans: W rows are k-contiguous (col-major B)
        bh[2*np][0] = t[0]; bh[2*np][1] = t[1]; bh[2*np+1][0] = t[2]; bh[2*np+1][1] = t[3];
        ldsm4(t, sWlB + off);
        bl[2*np][0] = t[0]; bl[2*np][1] = t[1]; bl[2*np+1][0] = t[2]; bl[2*np+1][1] = t[3];
      }
#pragma unroll
      for (int mt = 0; mt < 4; mt++)
#pragma unroll
        for (int nt = 0; nt < 4; nt++) {
          mma16816(acc[mt][nt], ah[mt], bh[nt]);
          mma16816(acc[mt][nt], ah[mt], bl[nt]);
          mma16816(acc[mt][nt], al[mt], bh[nt]);
        }
    }
  }

  // epilogue: frag (m16n8) lane layout: rows lr, lr+8; cols lc, lc+1
  const int lr = lane >> 2;
  const int lc = (lane & 3) << 1;
#pragma unroll
  for (int mt = 0; mt < 4; mt++) {
    const int row0 = m0 + warp_m * 64 + mt * 16 + lr;
#pragma unroll
    for (int nt = 0; nt < 4; nt++) {
      const int col = n0 + warp_n * 32 + nt * 8 + lc;
      const float b0 = bias[col], b1 = bias[col + 1];
      float v0 = acc[mt][nt][0] + b0;
      float v1 = acc[mt][nt][1] + b1;
      float v2 = acc[mt][nt][2] + b0;
      float v3 = acc[mt][nt][3] + b1;
      if (doSilu) { v0 = siluf(v0); v1 = siluf(v1); v2 = siluf(v2); v3 = siluf(v3); }
      *(float2*)(C + (size_t)row0 * DIMM + col)       = make_float2(v0, v1);
      *(float2*)(C + (size_t)(row0 + 8) * DIMM + col) = make_float2(v2, v3);
    }
  }
}

// ---------------- gate projections ----------------
__global__ __launch_bounds__(256) void gate_gemm(
    const float* __restrict__ X, const float* __restrict__ Wa, const float* __restrict__ ba,
    const float* __restrict__ Wb, const float* __restrict__ bbias,
    float* __restrict__ Ga, float* __restrict__ Gb)
{
  __shared__ float Xs[32][129];
  __shared__ float Ws[32][33];
  const int tid = threadIdx.x;
  const int m0  = blockIdx.x << 7;
  const int tm0 = (tid >> 4) << 3;
  const int tn0 = (tid & 15) << 1;

  float acc[8][2];
#pragma unroll
  for (int i = 0; i < 8; i++) { acc[i][0] = 0.f; acc[i][1] = 0.f; }

  for (int k0 = 0; k0 < 1024; k0 += 32) {
    __syncthreads();
#pragma unroll
    for (int ii = 0; ii < 4; ii++) {
      int idx = tid + (ii << 8);
      int rr = idx >> 3, c4 = (idx & 7) << 2;
      float4 v = *(const float4*)&X[(size_t)(m0 + rr) * DIMM + k0 + c4];
      Xs[c4+0][rr] = v.x; Xs[c4+1][rr] = v.y; Xs[c4+2][rr] = v.z; Xs[c4+3][rr] = v.w;
    }
    {
      int n = tid >> 3, c4 = (tid & 7) << 2;
      if (n < 32) {
        const float* wp = (n < 16) ? (Wa + (size_t)n * DIMM) : (Wb + (size_t)(n - 16) * DIMM);
        float4 v = *(const float4*)&wp[k0 + c4];
        Ws[c4+0][n] = v.x; Ws[c4+1][n] = v.y; Ws[c4+2][n] = v.z; Ws[c4+3][n] = v.w;
      }
    }
    __syncthreads();
#pragma unroll
    for (int kk = 0; kk < 32; kk++) {
      float wf0 = Ws[kk][tn0], wf1 = Ws[kk][tn0 + 1];
#pragma unroll
      for (int i = 0; i < 8; i++) {
        float av = Xs[kk][tm0 + i];
        acc[i][0] = fmaf(av, wf0, acc[i][0]);
        acc[i][1] = fmaf(av, wf1, acc[i][1]);
      }
    }
  }
#pragma unroll
  for (int j = 0; j < 2; j++) {
    int col = tn0 + j;
    float bi = (col < 16) ? ba[col] : bbias[col - 16];
    float* dst = (col < 16) ? Ga : Gb;
    int cc = col & 15;
#pragma unroll
    for (int i = 0; i < 8; i++) {
      int row = m0 + tm0 + i;
      dst[(size_t)row * 16 + cc] = sigmf(acc[i][j] + bi);
    }
  }
}

// ---------------- depthwise conv (K=4) + silu ----------------
__global__ __launch_bounds__(256) void conv_silu_kernel(
    const float* __restrict__ P, const float* __restrict__ wc, float* __restrict__ Y)
{
  const int c  = (blockIdx.x << 8) + threadIdx.x;
  const int b  = blockIdx.z;
  const int t0 = blockIdx.y << 7;
  const float w0 = wc[c*4+0], w1 = wc[c*4+1], w2 = wc[c*4+2], w3 = wc[c*4+3];
  const float* base  = P + (size_t)b * NN * DIMM + c;
  float*       ybase = Y + (size_t)b * NN * DIMM + c;
  float xm2 = (t0 >= 2) ? base[(size_t)(t0-2)*DIMM] : 0.f;
  float xm1 = (t0 >= 1) ? base[(size_t)(t0-1)*DIMM] : 0.f;
  float x0  = base[(size_t)t0 * DIMM];
#pragma unroll 4
  for (int t = t0; t < t0 + 128; t++) {
    float xp1 = (t + 1 < NN) ? base[(size_t)(t+1)*DIMM] : 0.f;
    float y = w0*xm2 + w1*xm1 + w2*x0 + w3*xp1;
    ybase[(size_t)t * DIMM] = siluf(y);
    xm2 = xm1; xm1 = x0; x0 = xp1;
  }
}

// ---------------- row l2norm (in place) ----------------
__global__ __launch_bounds__(256) void l2norm_kernel(float* __restrict__ X)
{
  __shared__ float red[8];
  float4* p = (float4*)(X + (size_t)blockIdx.x * DIMM);
  const int tid = threadIdx.x;
  float4 v = p[tid];
  float s = v.x*v.x + v.y*v.y + v.z*v.z + v.w*v.w;
#pragma unroll
  for (int o = 16; o > 0; o >>= 1) s += __shfl_xor_sync(0xffffffffu, s, o);
  if ((tid & 31) == 0) red[tid >> 5] = s;
  __syncthreads();
  float tot = red[0]+red[1]+red[2]+red[3]+red[4]+red[5]+red[6]+red[7];
  float inv = 1.f / (sqrtf(tot) + 1e-6f);
  v.x *= inv; v.y *= inv; v.z *= inv; v.w *= inv;
  p[tid] = v;
}

// ---------------- gated delta-rule scan ----------------
__global__ __launch_bounds__(256) void scan_kernel(
    const float* __restrict__ Q, const float* __restrict__ Kv, const float* __restrict__ V,
    const float* __restrict__ A, const float* __restrict__ Bg, float* __restrict__ O)
{
  __shared__ float shq[CH][64], shk[CH][64], shv[CH][64];
  __shared__ float sha[CH], shb[CH];
  __shared__ float mat[64][68];
  __shared__ float part[64][4];
  __shared__ float part2[64][4];
  __shared__ float coefsh[64];
  const int tid = threadIdx.x;
  const int e = tid & 63, g = tid >> 6;
  const int bh = blockIdx.x;
  const int b = bh >> 4, h = bh & 15;
  const size_t base = ((size_t)b * NN) * DIMM + h * 64;
  float S[16];
#pragma unroll
  for (int i = 0; i < 16; i++) S[i] = 0.f;

  for (int t0 = 0; t0 < NN; t0 += CH) {
    __syncthreads();
    for (int idx = tid; idx < CH*64; idx += 256) {
      int i = idx >> 6, ee = idx & 63;
      size_t off = base + (size_t)(t0 + i) * DIMM + ee;
      shq[i][ee] = Q[off]; shk[i][ee] = Kv[off]; shv[i][ee] = V[off];
    }
    if (tid < CH) {
      size_t off = ((size_t)b * NN + t0 + tid) * 16 + h;
      sha[tid] = A[off]; shb[tid] = Bg[off];
    }
    __syncthreads();

    for (int i = 0; i < CH; i++) {
      const float ke = shk[i][e];
      const float aT = sha[i], bT = shb[i];
#pragma unroll
      for (int j = 0; j < 16; j++) mat[16*g + j][e] = S[j] * ke;
      __syncthreads();
      const float4* rp = (const float4*)&mat[e][16*g];
      float4 p0 = rp[0], p1 = rp[1], p2 = rp[2], p3 = rp[3];
      part[e][g] = (p0.x+p0.y+p0.z+p0.w) + (p1.x+p1.y+p1.z+p1.w)
                 + (p2.x+p2.y+p2.z+p2.w) + (p3.x+p3.y+p3.z+p3.w);
      __syncthreads();
      if (g == 0) {
        float4 pr = *(const float4*)&part[e][0];
        float Sk = pr.x + pr.y + pr.z + pr.w;
        coefsh[e] = bT * (shv[i][e] - aT * Sk);
      }
      __syncthreads();
      float op = 0.f;
#pragma unroll
      for (int j4 = 0; j4 < 4; j4++) {
        float4 cf = *(const float4*)&coefsh[16*g + 4*j4];
        float4 qv = *(const float4*)&shq[i][16*g + 4*j4];
        int j = 4*j4;
        S[j+0] = aT*S[j+0] + cf.x*ke; op = fmaf(qv.x, S[j+0], op);
        S[j+1] = aT*S[j+1] + cf.y*ke; op = fmaf(qv.y, S[j+1], op);
        S[j+2] = aT*S[j+2] + cf.z*ke; op = fmaf(qv.z, S[j+2], op);
        S[j+3] = aT*S[j+3] + cf.w*ke; op = fmaf(qv.w, S[j+3], op);
      }
      part2[e][g] = op;
      __syncthreads();
      if (g == 0) {
        float4 pr = *(const float4*)&part2[e][0];
        O[base + (size_t)(t0 + i) * DIMM + e] = pr.x + pr.y + pr.z + pr.w;
      }
    }
  }
}

// ---------------- launch ----------------
extern "C" void kernel_launch(void* const* d_in, const int* in_sizes, int n_in,
                              void* d_out, int out_size) {
  const float* x      = (const float*)d_in[0];
  const float* Wq     = (const float*)d_in[1];
  const float* bq     = (const float*)d_in[2];
  const float* Wk     = (const float*)d_in[3];
  const float* bk     = (const float*)d_in[4];
  const float* Wv     = (const float*)d_in[5];
  const float* bv     = (const float*)d_in[6];
  const float* Wa     = (const float*)d_in[7];
  const float* ba     = (const float*)d_in[8];
  const float* Wb     = (const float*)d_in[9];
  const float* bb     = (const float*)d_in[10];
  const float* conv_q = (const float*)d_in[11];
  const float* conv_k = (const float*)d_in[12];
  const float* conv_v = (const float*)d_in[13];
  const float* Wo     = (const float*)d_in[14];
  const float* bo     = (const float*)d_in[15];
  float* out = (float*)d_out;

  void *pq, *pk, *pv, *q, *k, *v, *o, *ga, *gb, *xhi, *xlo, *ohi, *olo, *whi, *wlo;
  cudaGetSymbolAddress(&pq, g_pq);
  cudaGetSymbolAddress(&pk, g_pk);
  cudaGetSymbolAddress(&pv, g_pv);
  cudaGetSymbolAddress(&q,  g_q);
  cudaGetSymbolAddress(&v,  g_v);
  cudaGetSymbolAddress(&k,  g_k);
  cudaGetSymbolAddress(&o,  g_o);
  cudaGetSymbolAddress(&ga, g_a);
  cudaGetSymbolAddress(&gb, g_b);
  cudaGetSymbolAddress(&xhi, g_xhi);
  cudaGetSymbolAddress(&xlo, g_xlo);
  cudaGetSymbolAddress(&ohi, g_ohi);
  cudaGetSymbolAddress(&olo, g_olo);
  cudaGetSymbolAddress(&whi, g_whi);
  cudaGetSymbolAddress(&wlo, g_wlo);

  const int NW4 = (DIMM * DIMM) / 4;
  const int NX4 = (MM * DIMM) / 4;
  dim3 ggrid(8, MM / 128);

  split_kernel<<<(NX4 + 255) / 256, 256>>>(x, (__nv_bfloat16*)xhi, (__nv_bfloat16*)xlo, NX4);

  split_kernel<<<(NW4 + 255) / 256, 256>>>(Wq, (__nv_bfloat16*)whi, (__nv_bfloat16*)wlo, NW4);
  gemm_mma<<<ggrid, 256>>>((const __nv_bfloat16*)xhi, (const __nv_bfloat16*)xlo,
                           (const __nv_bfloat16*)whi, (const __nv_bfloat16*)wlo,
                           bq, (float*)pq, 1);
  split_kernel<<<(NW4 + 255) / 256, 256>>>(Wk, (__nv_bfloat16*)whi, (__nv_bfloat16*)wlo, NW4);
  gemm_mma<<<ggrid, 256>>>((const __nv_bfloat16*)xhi, (const __nv_bfloat16*)xlo,
                           (const __nv_bfloat16*)whi, (const __nv_bfloat16*)wlo,
                           bk, (float*)pk, 1);
  split_kernel<<<(NW4 + 255) / 256, 256>>>(Wv, (__nv_bfloat16*)whi, (__nv_bfloat16*)wlo, NW4);
  gemm_mma<<<ggrid, 256>>>((const __nv_bfloat16*)xhi, (const __nv_bfloat16*)xlo,
                           (const __nv_bfloat16*)whi, (const __nv_bfloat16*)wlo,
                           bv, (float*)pv, 1);

  gate_gemm<<<MM / 128, 256>>>(x, Wa, ba, Wb, bb, (float*)ga, (float*)gb);

  dim3 cgrid(DIMM / 256, NN / 128, BB);
  conv_silu_kernel<<<cgrid, 256>>>((const float*)pq, conv_q, (float*)q);
  conv_silu_kernel<<<cgrid, 256>>>((const float*)pk, conv_k, (float*)k);
  conv_silu_kernel<<<cgrid, 256>>>((const float*)pv, conv_v, (float*)v);

  l2norm_kernel<<<MM, 256>>>((float*)q);
  l2norm_kernel<<<MM, 256>>>((float*)k);

  scan_kernel<<<BB * HH, 256>>>((const float*)q, (const float*)k, (const float*)v,
                                (const float*)ga, (const float*)gb, (float*)o);

  split_kernel<<<(NX4 + 255) / 256, 256>>>((const float*)o, (__nv_bfloat16*)ohi, (__nv_bfloat16*)olo, NX4);
  split_kernel<<<(NW4 + 255) / 256, 256>>>(Wo, (__nv_bfloat16*)whi, (__nv_bfloat16*)wlo, NW4);
  gemm_mma<<<ggrid, 256>>>((const __nv_bfloat16*)ohi, (const __nv_bfloat16*)olo,
                           (const __nv_bfloat16*)whi, (const __nv_bfloat16*)wlo,
                           bo, out, 0);
}